// round 4
// baseline (speedup 1.0000x reference)
#include <cuda_runtime.h>

// EmbeddingRowAdapter: out[t,:] = E[ids[t],:] + (pos[ids[t]]>=0 ? A[pos]·B^T : 0)
// V=100000, D=256, M=8192, R=32, tokens = 204800

constexpr int D = 256;
constexpr int R = 32;
constexpr int V_MAX = 100000;

__device__ int   g_pos[V_MAX];      // .bss zero-init; slots not in idx stay 0
__device__ int   g_is64;            // 1 if ids/idx stored as int64, 0 if int32
__device__ float g_Bt[R][D];        // B transposed: g_Bt[r][d] = Bm[d*R + r]

// idx holds unique row ids; detect storage width: int64 little-endian read as
// int32 pairs -> word[1]==0 for small positive values; int32 -> nonzero.
__device__ __forceinline__ bool detect_is64(const void* idx, int M) {
    return (M > 1) && (((const int*)idx)[1] == 0);
}

// Single fused setup kernel: B transpose + pos scatter. No init sweep over V —
// main kernel validates pos entries via idx[p]==id instead.
__global__ void setup_kernel(const void* __restrict__ idx,
                             const float* __restrict__ Bm, int M) {
    const int i = blockIdx.x * blockDim.x + threadIdx.x;
    const bool is64 = detect_is64(idx, M);
    if (i == 0) g_is64 = is64 ? 1 : 0;
    if (i < D * R) g_Bt[i & (R - 1)][i >> 5] = Bm[i];   // i = d*R + r
    if (i < M) {
        long long v = is64 ? ((const long long*)idx)[i]
                           : (long long)((const int*)idx)[i];
        if (v >= 0 && v < V_MAX) g_pos[v] = i;
    }
}

// 256-bit E-row load, L2 evict_last (keeps E resident vs streaming stores).
// sm_103 requires .v8.b32 (or .v4.b64) for the evict_last modifier.
__device__ __forceinline__ void ldg256_evict_last(const float* p, float v[8]) {
    unsigned r0, r1, r2, r3, r4, r5, r6, r7;
    asm("ld.global.nc.L2::evict_last.v8.b32 {%0,%1,%2,%3,%4,%5,%6,%7}, [%8];"
        : "=r"(r0), "=r"(r1), "=r"(r2), "=r"(r3),
          "=r"(r4), "=r"(r5), "=r"(r6), "=r"(r7)
        : "l"(p));
    v[0] = __uint_as_float(r0); v[1] = __uint_as_float(r1);
    v[2] = __uint_as_float(r2); v[3] = __uint_as_float(r3);
    v[4] = __uint_as_float(r4); v[5] = __uint_as_float(r5);
    v[6] = __uint_as_float(r6); v[7] = __uint_as_float(r7);
}

// LoRA delta for one token: v[0..8) += A[p,:] @ Bt[:, 8*lane .. 8*lane+8)
__device__ __forceinline__ void add_delta(float v[8],
                                          const float* __restrict__ A,
                                          int p, int lane) {
    const float4* arow = reinterpret_cast<const float4*>(A + (size_t)p * R);
    float acc[8] = {0.f, 0.f, 0.f, 0.f, 0.f, 0.f, 0.f, 0.f};
#pragma unroll
    for (int j = 0; j < R / 4; j++) {
        float4 av = __ldg(arow + j);
        float as[4] = {av.x, av.y, av.z, av.w};
#pragma unroll
        for (int rr = 0; rr < 4; rr++) {
            int r = 4 * j + rr;
            float4 b0 = *reinterpret_cast<const float4*>(&g_Bt[r][8 * lane]);
            float4 b1 = *reinterpret_cast<const float4*>(&g_Bt[r][8 * lane + 4]);
            acc[0] = fmaf(as[rr], b0.x, acc[0]);
            acc[1] = fmaf(as[rr], b0.y, acc[1]);
            acc[2] = fmaf(as[rr], b0.z, acc[2]);
            acc[3] = fmaf(as[rr], b0.w, acc[3]);
            acc[4] = fmaf(as[rr], b1.x, acc[4]);
            acc[5] = fmaf(as[rr], b1.y, acc[5]);
            acc[6] = fmaf(as[rr], b1.z, acc[6]);
            acc[7] = fmaf(as[rr], b1.w, acc[7]);
        }
    }
#pragma unroll
    for (int i = 0; i < 8; i++) v[i] += acc[i];
}

// One warp owns a 32-token tile. ids/pos gathered coalesced up front
// (lane-per-token, distributed via shfl). pos validity = idx[p]==id.
// Inner loop: 4 tokens/iter, each a single 256-bit E load (4 in flight).
__global__ __launch_bounds__(128)
void adapter_kernel(const void* __restrict__ ids,
                    const void* __restrict__ idx,
                    const float* __restrict__ E,
                    const float* __restrict__ A,
                    float* __restrict__ out,
                    int n_tokens, int M)
{
    const int lane   = threadIdx.x & 31;
    const int warp   = (blockIdx.x * blockDim.x + threadIdx.x) >> 5;
    const int nwarps = (gridDim.x * blockDim.x) >> 5;
    const int is64   = g_is64;

    for (int t0 = warp * 32; t0 < n_tokens; t0 += nwarps * 32) {
        // Coalesced gather of this tile's ids + validated pos (token per lane).
        int tl = t0 + lane;
        int myid = 0, mypos = -1;
        if (tl < n_tokens) {
            long long v = is64 ? ((const long long*)ids)[tl]
                               : (long long)((const int*)ids)[tl];
            myid = (int)v;
            int p = g_pos[myid];
            if (p >= 0 && p < M) {
                long long iv = is64 ? ((const long long*)idx)[p]
                                    : (long long)((const int*)idx)[p];
                if (iv == (long long)myid) mypos = p;
            }
        }
        const int lim = min(32, n_tokens - t0);

        for (int k = 0; k < lim; k += 4) {
            int id_[4], p_[4];
            bool have[4];
#pragma unroll
            for (int u = 0; u < 4; u++) {
                have[u] = (k + u) < lim;
                int src = (k + u) & 31;
                id_[u] = __shfl_sync(0xffffffffu, myid,  src);
                p_[u]  = __shfl_sync(0xffffffffu, mypos, src);
            }

            // Batch E loads: one 256-bit ld per token, 4 independent in flight.
            float v[4][8];
#pragma unroll
            for (int u = 0; u < 4; u++) {
                if (have[u])
                    ldg256_evict_last(E + (size_t)id_[u] * D + 8 * lane, v[u]);
            }

            // Adapter delta (warp-uniform branch) + streaming stores.
#pragma unroll
            for (int u = 0; u < 4; u++) {
                if (!have[u]) continue;
                if (p_[u] >= 0) add_delta(v[u], A, p_[u], lane);
                float4* o = reinterpret_cast<float4*>(
                    out + (size_t)(t0 + k + u) * D + 8 * lane);
                __stcs(o,     make_float4(v[u][0], v[u][1], v[u][2], v[u][3]));
                __stcs(o + 1, make_float4(v[u][4], v[u][5], v[u][6], v[u][7]));
            }
        }
    }
}

extern "C" void kernel_launch(void* const* d_in, const int* in_sizes, int n_in,
                              void* d_out, int out_size)
{
    const void*  ids = d_in[0];                 // [B,L] int32 or int64
    const void*  idx = d_in[1];                 // [M]   int32 or int64
    const float* E   = (const float*)d_in[2];   // [V,D]
    const float* A   = (const float*)d_in[3];   // [M,R]
    const float* Bm  = (const float*)d_in[4];   // [D,R]
    float*       out = (float*)d_out;

    const int n_tokens = in_sizes[0];
    const int M        = in_sizes[1];
    const int setup_n  = (M > D * R) ? M : D * R;

    setup_kernel<<<(setup_n + 255) / 256, 256>>>(idx, Bm, M);

    // 6400 32-token tiles; 1600 blocks x 4 warps = exactly one tile per warp.
    int n_tiles  = (n_tokens + 31) / 32;
    int n_blocks = (n_tiles + 3) / 4;
    adapter_kernel<<<n_blocks, 128>>>(ids, idx, E, A, out, n_tokens, M);
}